// round 10
// baseline (speedup 1.0000x reference)
#include <cuda_runtime.h>
#include <cstdint>

#define BB   128
#define TT   500
#define NIN  700
#define NH   200
#define NOUT 20
#define NROWS (BB*TT)          // 64000
#define CAP  256               // max active inputs per row (x4-padded with 700)

// -------- scratch (static __device__ allocations: allowed) -----------------
__device__ unsigned short g_idx[(size_t)NROWS * CAP];
__device__ int            g_cnt[NROWS];
__device__ float          g_ff[(size_t)NROWS * NH];     // cur1_ff = x@W1^T + b1

// ===========================================================================
// P0: compact active input indices per (b,t) row; pad list to x4 with 700.
// DRAM-bound (~35us floor).
// ===========================================================================
__global__ __launch_bounds__(256) void k_compact(const float* __restrict__ x)
{
    int wid  = threadIdx.x >> 5, lane = threadIdx.x & 31;
    int row  = blockIdx.x * 8 + wid;
    if (row >= NROWS) return;
    const float* xr = x + (size_t)row * NIN;
    unsigned short* out = g_idx + (size_t)row * CAP;
    unsigned lt = (1u << lane) - 1u;
    int cnt = 0;
#pragma unroll
    for (int c = 0; c < (NIN + 31) / 32; c++) {
        int i = c * 32 + lane;
        float v = (i < NIN) ? xr[i] : 0.f;
        bool a = v > 0.5f;
        unsigned m = __ballot_sync(0xffffffffu, a);
        if (a) {
            int pos = cnt + __popc(m & lt);
            if (pos < CAP) out[pos] = (unsigned short)i;
        }
        cnt += __popc(m);
    }
    if (lane == 0) {
        int c = (cnt < CAP) ? cnt : CAP;
        g_cnt[row] = c;
        int cp = c;
        while ((cp & 3) && cp < CAP) out[cp++] = 700;   // pad -> zero row
    }
}

// ===========================================================================
// P1: cur1_ff (unchanged from R7: ~293us measured).
// ===========================================================================
#define P1_HC     50
#define P1_STRIDE 52
#define P1_WSLOT  64
#define OFF_BUF   (701 * P1_STRIDE)
#define P1_SMEM   ((OFF_BUF + 16 * P1_WSLOT * 2) * 4)
#define P1_GROUPS 128
#define P1_RPC    (NROWS / P1_GROUPS)

__global__ __launch_bounds__(512) void k_ff(const float* __restrict__ W1,
                                            const float* __restrict__ b1)
{
    extern __shared__ float s[];
    int tid = threadIdx.x, wid = tid >> 5, lane = tid & 31;
    int h0 = blockIdx.x * P1_HC;

    for (int i = tid; i < P1_HC * NIN; i += 512) {
        int hh = i / NIN, n = i - hh * NIN;
        s[n * P1_STRIDE + hh] = W1[(h0 + hh) * NIN + n];
    }
    for (int i = tid; i < P1_STRIDE; i += 512) s[700 * P1_STRIDE + i] = 0.f;
    __syncthreads();

    uint2* swbuf = (uint2*)(s + OFF_BUF) + wid * P1_WSLOT;
    const uint2* sbuf2 = (const uint2*)swbuf;

    int hh2 = 2 * lane;
    bool act = (lane < 25);
    float bb0 = 0.f, bb1 = 0.f;
    if (act) { bb0 = b1[h0 + hh2]; bb1 = b1[h0 + hh2 + 1]; }

    int base = blockIdx.y * P1_RPC;
    int lim  = base + P1_RPC; if (lim > NROWS) lim = NROWS;

    int row = base + wid;
    if (row >= lim) return;

    int  cnt_c = g_cnt[row];
    uint2 rA   = ((const uint2*)(g_idx + (size_t)row * CAP))[lane];

    while (row < lim) {
        int rn = row + 16;
        int  cnt_n = 0;
        uint2 nA = make_uint2(0u, 0u);
        if (rn < lim) {
            cnt_n = g_cnt[rn];
            nA = ((const uint2*)(g_idx + (size_t)rn * CAP))[lane];
        }

        swbuf[lane] = rA;
        if (cnt_c > 128)
            swbuf[32 + lane] = ((const uint2*)(g_idx + (size_t)row * CAP))[32 + lane];
        __syncwarp();

        float c0a = 0.f, c1a = 0.f, c0b = 0.f, c1b = 0.f;
        int it = (cnt_c + 3) >> 2;
#pragma unroll 2
        for (int k = 0; k < it; k++) {
            uint2 u = sbuf2[k];
            int j0 = u.x & 0xffff, j1 = u.x >> 16;
            int j2 = u.y & 0xffff, j3 = u.y >> 16;
            if (act) {
                float2 v0 = *(const float2*)&s[j0 * P1_STRIDE + hh2];
                float2 v1 = *(const float2*)&s[j1 * P1_STRIDE + hh2];
                float2 v2 = *(const float2*)&s[j2 * P1_STRIDE + hh2];
                float2 v3 = *(const float2*)&s[j3 * P1_STRIDE + hh2];
                c0a += v0.x + v1.x;  c0b += v2.x + v3.x;
                c1a += v0.y + v1.y;  c1b += v2.y + v3.y;
            }
        }
        if (act) {
            float2 o; o.x = (c0a + c0b) + bb0; o.y = (c1a + c1b) + bb1;
            *(float2*)&g_ff[(size_t)row * NH + h0 + hh2] = o;
        }
        __syncwarp();

        row = rn; cnt_c = cnt_n; rA = nA;
    }
}

// ===========================================================================
// P2: 9-warp CTA per batch (288 threads), h-sliced.
// Warps 0-7: lane<25 owns h = w*25+lane. Per step: gather over 8 spike-list
// segments (LDS.32+FADD per spike, 4 acc chains), own-state update, own
// ballot, write own segment of list[q]. Warp 8: lanes 0-19 own one output,
// gather W2 over same list (layer-2 deferred 1 step + epilogue), softmax
// in-warp. ONE __syncthreads per step.
// R9 bug fixed: list needs [2][8][32] ushorts = 256 floats (was 128).
// ===========================================================================
#define S_W2    (201 * NH)                       // floats: W2^T [201][20]
#define S_CNT   (S_W2 + 201 * NOUT)              // ints [2][8]
#define S_LIST  (S_CNT + 16)                     // ushorts [2][8][32]
#define P2_SMEM ((S_LIST + 256) * 4)             // 512 ushorts = 256 floats

__global__ __launch_bounds__(288) void k_snn(
    const float* __restrict__ Wfb,  const float* __restrict__ bfb,
    const float* __restrict__ W2,   const float* __restrict__ b2,
    const float* __restrict__ alpha1, const float* __restrict__ beta1,
    const float* __restrict__ thr1,
    const float* __restrict__ alpha2, const float* __restrict__ beta2,
    const float* __restrict__ thr2,
    float* __restrict__ out)
{
    extern __shared__ float sm[];
    float* sWfb = sm;                            // [201][200], row 200 = zeros
    float* sW2  = sm + S_W2;                     // [201][20],  row 200 = zeros
    int*   scnt = (int*)(sm + S_CNT);            // [2][8]
    unsigned short* slist = (unsigned short*)(sm + S_LIST);   // [2][8][32]

    int tid = threadIdx.x, w = tid >> 5, lane = tid & 31;
    int b = blockIdx.x;
    unsigned lt = (1u << lane) - 1u;
    bool isH  = (w < 8) && (lane < 25);          // owns hidden unit
    bool isO  = (w == 8) && (lane < 20);         // owns output unit
    int h_own = w * 25 + lane;                   // valid when isH

    // ---- load transposed weights (one-time) ----
    for (int i = tid; i < NH * NH; i += 288) {
        int h = i / NH, j = i - h * NH;
        sWfb[j * NH + h] = Wfb[i];               // sWfb[j][h] = Wfb[h][j]
    }
    for (int i = tid; i < NH; i += 288) sWfb[200 * NH + i] = 0.f;
    for (int i = tid; i < NOUT * NH; i += 288) {
        int o = i / NH, j = i - o * NH;
        sW2[j * NOUT + o] = W2[i];
    }
    for (int i = tid; i < NOUT; i += 288) sW2[200 * NOUT + i] = 0.f;
    if (tid < 16) scnt[tid] = 0;

    // ---- per-lane parameters ----
    float a1v = 0.f, b1v = 0.f, t1v = 1.f, fb = 0.f;
    const float* ffbase = g_ff + (size_t)b * TT * NH;
    if (isH) {
        a1v = alpha1[h_own]; b1v = beta1[h_own];
        t1v = thr1[h_own];   fb  = bfb[h_own];
    }
    float a2v = 0.f, be2 = 0.f, t2v = 1.f, bb2 = 0.f;
    if (isO) { a2v = alpha2[lane]; be2 = beta2[lane]; t2v = thr2[lane]; bb2 = b2[lane]; }

    float syn1 = 0.f, mem1 = 0.f;
    float syn2 = 0.f, mem2 = 0.f, rmax = __int_as_float(0xff800000u);

    __syncthreads();

    float ff = isH ? ffbase[h_own] : 0.f;
    float nf = 0.f;

    for (int t = 0; t < TT; t++) {
        int p = t & 1, q = p ^ 1;

        // prefetch next step's feedforward current
        if (isH && t + 1 < TT) nf = ffbase[(t + 1) * NH + h_own];

        if (w < 8) {
            // ---- gather own h over all 8 segments of list[p] ----
            float ac0 = 0.f, ac1 = 0.f, ac2 = 0.f, ac3 = 0.f;
            const float* wrow = sWfb + h_own;    // + j*200
#pragma unroll 1
            for (int s = 0; s < 8; s++) {
                int c = scnt[p * 8 + s];
                const unsigned short* seg = &slist[(p * 8 + s) * 32];
                int it = (c + 3) >> 2;
                for (int k = 0; k < it; k++) {
                    uint2 u = *(const uint2*)&seg[4 * k];   // 4 indices, uniform
                    int j0 = u.x & 0xffff, j1 = u.x >> 16;
                    int j2 = u.y & 0xffff, j3 = u.y >> 16;
                    if (isH) {
                        ac0 += wrow[j0 * NH];
                        ac1 += wrow[j1 * NH];
                        ac2 += wrow[j2 * NH];
                        ac3 += wrow[j3 * NH];
                    }
                }
            }
            // ---- own-state update + spike ----
            bool sp = false;
            if (isH) {
                float cur = (ac0 + ac1) + (ac2 + ac3) + ff + fb;
                syn1 = a1v * syn1 + cur;
                float r = (mem1 > t1v) ? t1v : 0.f;
                mem1 = b1v * mem1 + syn1 - r;
                sp = mem1 > t1v;
            }
            // ---- build own segment of list[q] ----
            unsigned m = __ballot_sync(0xffffffffu, sp);
            int nc = __popc(m);
            unsigned short* segq = &slist[(q * 8 + w) * 32];
            if (sp) segq[__popc(m & lt)] = (unsigned short)h_own;
            if (lane == 0) {
                scnt[q * 8 + w] = nc;
                int cp = nc;
                while (cp & 3) segq[cp++] = 200;            // pad -> zero row
            }
        } else {
            // ---- warp 8: layer-2 gather over list[p] (spikes of t-1) ----
            float ac0 = 0.f, ac1 = 0.f, ac2 = 0.f, ac3 = 0.f;
            const float* w2row = sW2 + lane;     // + j*20
#pragma unroll 1
            for (int s = 0; s < 8; s++) {
                int c = scnt[p * 8 + s];
                const unsigned short* seg = &slist[(p * 8 + s) * 32];
                int it = (c + 3) >> 2;
                for (int k = 0; k < it; k++) {
                    uint2 u = *(const uint2*)&seg[4 * k];
                    int j0 = u.x & 0xffff, j1 = u.x >> 16;
                    int j2 = u.y & 0xffff, j3 = u.y >> 16;
                    if (isO) {
                        ac0 += w2row[j0 * NOUT];
                        ac1 += w2row[j1 * NOUT];
                        ac2 += w2row[j2 * NOUT];
                        ac3 += w2row[j3 * NOUT];
                    }
                }
            }
            if (t > 0 && isO) {                  // finalize step t-1
                float cur2 = (ac0 + ac1) + (ac2 + ac3) + bb2;
                syn2 = a2v * syn2 + cur2;
                float r2 = (mem2 > t2v) ? t2v : 0.f;
                mem2 = be2 * mem2 + syn2 - r2;
                rmax = fmaxf(rmax, mem2);
            }
        }
        __syncthreads();                         // list[q] ready for all
        ff = nf;
    }

    // ---- epilogue (warp 8): layer-2 for step TT-1, then softmax ----
    if (w == 8) {
        int pf = TT & 1;
        float ac0 = 0.f, ac1 = 0.f, ac2 = 0.f, ac3 = 0.f;
        const float* w2row = sW2 + lane;
        for (int s = 0; s < 8; s++) {
            int c = scnt[pf * 8 + s];
            const unsigned short* seg = &slist[(pf * 8 + s) * 32];
            int it = (c + 3) >> 2;
            for (int k = 0; k < it; k++) {
                uint2 u = *(const uint2*)&seg[4 * k];
                int j0 = u.x & 0xffff, j1 = u.x >> 16;
                int j2 = u.y & 0xffff, j3 = u.y >> 16;
                if (isO) {
                    ac0 += w2row[j0 * NOUT];
                    ac1 += w2row[j1 * NOUT];
                    ac2 += w2row[j2 * NOUT];
                    ac3 += w2row[j3 * NOUT];
                }
            }
        }
        if (isO) {
            float cur2 = (ac0 + ac1) + (ac2 + ac3) + bb2;
            syn2 = a2v * syn2 + cur2;
            float r2 = (mem2 > t2v) ? t2v : 0.f;
            mem2 = be2 * mem2 + syn2 - r2;
            rmax = fmaxf(rmax, mem2);
        }
        // softmax over 20 outputs, entirely within warp 8
        float v = isO ? rmax : __int_as_float(0xff800000u);
#pragma unroll
        for (int d = 16; d; d >>= 1) v = fmaxf(v, __shfl_xor_sync(0xffffffffu, v, d));
        float e = isO ? expf(rmax - v) : 0.f;
        float ssum = e;
#pragma unroll
        for (int d = 16; d; d >>= 1) ssum += __shfl_xor_sync(0xffffffffu, ssum, d);
        if (isO) out[b * NOUT + lane] = e / ssum;
    }
}

// ===========================================================================
extern "C" void kernel_launch(void* const* d_in, const int* in_sizes, int n_in,
                              void* d_out, int out_size)
{
    const float* x      = (const float*)d_in[0];
    const float* W1     = (const float*)d_in[1];
    const float* b1     = (const float*)d_in[2];
    const float* Wfb    = (const float*)d_in[3];
    const float* bfb    = (const float*)d_in[4];
    const float* W2     = (const float*)d_in[5];
    const float* b2     = (const float*)d_in[6];
    const float* alpha1 = (const float*)d_in[7];
    const float* beta1  = (const float*)d_in[8];
    const float* thr1   = (const float*)d_in[9];
    const float* alpha2 = (const float*)d_in[10];
    const float* beta2  = (const float*)d_in[11];
    const float* thr2   = (const float*)d_in[12];
    float* out = (float*)d_out;

    cudaFuncSetAttribute(k_ff,  cudaFuncAttributeMaxDynamicSharedMemorySize, P1_SMEM);
    cudaFuncSetAttribute(k_snn, cudaFuncAttributeMaxDynamicSharedMemorySize, P2_SMEM);

    k_compact<<<NROWS / 8, 256>>>(x);
    k_ff<<<dim3(4, P1_GROUPS), 512, P1_SMEM>>>(W1, b1);
    k_snn<<<BB, 288, P2_SMEM>>>(Wfb, bfb, W2, b2,
                                alpha1, beta1, thr1,
                                alpha2, beta2, thr2, out);
}

// round 11
// speedup vs baseline: 1.2849x; 1.2849x over previous
#include <cuda_runtime.h>
#include <cstdint>

#define BB   128
#define TT   500
#define NIN  700
#define NH   200
#define NOUT 20
#define NROWS (BB*TT)          // 64000
#define CAP  256               // max active inputs per row (x4-padded with 700)

// -------- scratch (static __device__ allocations: allowed) -----------------
__device__ unsigned short g_idx[(size_t)NROWS * CAP];
__device__ int            g_cnt[NROWS];
__device__ float          g_ff[(size_t)NROWS * NH];     // cur1_ff = x@W1^T + b1

// ===========================================================================
// P0: compact active input indices per (b,t) row; pad list to x4 with 700.
// DRAM-bound (~35us floor).
// ===========================================================================
__global__ __launch_bounds__(256) void k_compact(const float* __restrict__ x)
{
    int wid  = threadIdx.x >> 5, lane = threadIdx.x & 31;
    int row  = blockIdx.x * 8 + wid;
    if (row >= NROWS) return;
    const float* xr = x + (size_t)row * NIN;
    unsigned short* out = g_idx + (size_t)row * CAP;
    unsigned lt = (1u << lane) - 1u;
    int cnt = 0;
#pragma unroll
    for (int c = 0; c < (NIN + 31) / 32; c++) {
        int i = c * 32 + lane;
        float v = (i < NIN) ? xr[i] : 0.f;
        bool a = v > 0.5f;
        unsigned m = __ballot_sync(0xffffffffu, a);
        if (a) {
            int pos = cnt + __popc(m & lt);
            if (pos < CAP) out[pos] = (unsigned short)i;
        }
        cnt += __popc(m);
    }
    if (lane == 0) {
        int c = (cnt < CAP) ? cnt : CAP;
        g_cnt[row] = c;
        int cp = c;
        while ((cp & 3) && cp < CAP) out[cp++] = 700;   // pad -> zero row
    }
}

// ===========================================================================
// P1: cur1_ff (unchanged from R7: ~293us measured).
// ===========================================================================
#define P1_HC     50
#define P1_STRIDE 52
#define P1_WSLOT  64
#define OFF_BUF   (701 * P1_STRIDE)
#define P1_SMEM   ((OFF_BUF + 16 * P1_WSLOT * 2) * 4)
#define P1_GROUPS 128
#define P1_RPC    (NROWS / P1_GROUPS)

__global__ __launch_bounds__(512) void k_ff(const float* __restrict__ W1,
                                            const float* __restrict__ b1)
{
    extern __shared__ float s[];
    int tid = threadIdx.x, wid = tid >> 5, lane = tid & 31;
    int h0 = blockIdx.x * P1_HC;

    for (int i = tid; i < P1_HC * NIN; i += 512) {
        int hh = i / NIN, n = i - hh * NIN;
        s[n * P1_STRIDE + hh] = W1[(h0 + hh) * NIN + n];
    }
    for (int i = tid; i < P1_STRIDE; i += 512) s[700 * P1_STRIDE + i] = 0.f;
    __syncthreads();

    uint2* swbuf = (uint2*)(s + OFF_BUF) + wid * P1_WSLOT;
    const uint2* sbuf2 = (const uint2*)swbuf;

    int hh2 = 2 * lane;
    bool act = (lane < 25);
    float bb0 = 0.f, bb1 = 0.f;
    if (act) { bb0 = b1[h0 + hh2]; bb1 = b1[h0 + hh2 + 1]; }

    int base = blockIdx.y * P1_RPC;
    int lim  = base + P1_RPC; if (lim > NROWS) lim = NROWS;

    int row = base + wid;
    if (row >= lim) return;

    int  cnt_c = g_cnt[row];
    uint2 rA   = ((const uint2*)(g_idx + (size_t)row * CAP))[lane];

    while (row < lim) {
        int rn = row + 16;
        int  cnt_n = 0;
        uint2 nA = make_uint2(0u, 0u);
        if (rn < lim) {
            cnt_n = g_cnt[rn];
            nA = ((const uint2*)(g_idx + (size_t)rn * CAP))[lane];
        }

        swbuf[lane] = rA;
        if (cnt_c > 128)
            swbuf[32 + lane] = ((const uint2*)(g_idx + (size_t)row * CAP))[32 + lane];
        __syncwarp();

        float c0a = 0.f, c1a = 0.f, c0b = 0.f, c1b = 0.f;
        int it = (cnt_c + 3) >> 2;
#pragma unroll 2
        for (int k = 0; k < it; k++) {
            uint2 u = sbuf2[k];
            int j0 = u.x & 0xffff, j1 = u.x >> 16;
            int j2 = u.y & 0xffff, j3 = u.y >> 16;
            if (act) {
                float2 v0 = *(const float2*)&s[j0 * P1_STRIDE + hh2];
                float2 v1 = *(const float2*)&s[j1 * P1_STRIDE + hh2];
                float2 v2 = *(const float2*)&s[j2 * P1_STRIDE + hh2];
                float2 v3 = *(const float2*)&s[j3 * P1_STRIDE + hh2];
                c0a += v0.x + v1.x;  c0b += v2.x + v3.x;
                c1a += v0.y + v1.y;  c1b += v2.y + v3.y;
            }
        }
        if (act) {
            float2 o; o.x = (c0a + c0b) + bb0; o.y = (c1a + c1b) + bb1;
            *(float2*)&g_ff[(size_t)row * NH + h0 + hh2] = o;
        }
        __syncwarp();

        row = rn; cnt_c = cnt_n; rA = nA;
    }
}

// ===========================================================================
// P2 (REWRITTEN): 2-warp CTA per batch, h-split + COMPLEMENT-LIST gather.
// warp0: h in [0,128) as float4/lane. warp1: h in [128,200) (lanes 0..17) +
// layer-2 (lanes 0..19) + softmax. Both warps walk the whole spike list
// (both segments) with next-quad preload (software pipeline) and packed
// add.rn.f32x2 accumulators. Adaptive: if >100 neurons spiked, store the
// NON-spikers and compute cur = rowsum - gather. 2 barriers/step.
// ===========================================================================
#define S2_W2    (201 * NH)                  // float offset: W2^T [201][20]
#define S2_CNT   (S2_W2 + 201 * NOUT)        // 2 ints
#define S2_LIST  (S2_CNT + 2)                // 184 ushorts (seg0:104, seg1:80)
#define SEG1_OFF 104
#define P2_SMEM  ((S2_LIST + 92) * 4)        // 177,256 B

#define ADD2(acc, v) asm("add.rn.f32x2 %0, %0, %1;" : "+l"(acc) : "l"(v))

__global__ __launch_bounds__(64) void k_snn(
    const float* __restrict__ Wfb,  const float* __restrict__ bfb,
    const float* __restrict__ W2,   const float* __restrict__ b2,
    const float* __restrict__ alpha1, const float* __restrict__ beta1,
    const float* __restrict__ thr1,
    const float* __restrict__ alpha2, const float* __restrict__ beta2,
    const float* __restrict__ thr2,
    float* __restrict__ out)
{
    extern __shared__ float sm[];
    float* sWfb = sm;                        // [201][200], row 200 = zeros
    float* sW2  = sm + S2_W2;                // [201][20],  row 200 = zeros
    int*   scnt = (int*)(sm + S2_CNT);       // [2]
    unsigned short* slist = (unsigned short*)(sm + S2_LIST);

    int tid = threadIdx.x, w = tid >> 5, lane = tid & 31;
    int b = blockIdx.x;
    unsigned lt = (1u << lane) - 1u;

    // ---- load transposed weights ----
    for (int i = tid; i < NH * NH; i += 64) {
        int h = i / NH, j = i - h * NH;
        sWfb[j * NH + h] = Wfb[i];
    }
    for (int i = tid; i < NH; i += 64) sWfb[200 * NH + i] = 0.f;
    for (int i = tid; i < NOUT * NH; i += 64) {
        int o = i / NH, j = i - o * NH;
        sW2[j * NOUT + o] = W2[i];
    }
    for (int i = tid; i < NOUT; i += 64) sW2[200 * NOUT + i] = 0.f;
    if (tid < 2) scnt[tid] = 0;
    __syncthreads();

    bool isB = (w == 1) && (lane < 18);
    bool isO = (w == 1) && (lane < 20);
    bool valid = (w == 0) || isB;
    int hbase = (w == 0) ? 4 * lane : 128 + 4 * lane;
    int rowoff = (w == 0) ? lane : 32 + lane;            // ull2 element in row

    const float4 f4z = make_float4(0.f, 0.f, 0.f, 0.f);
    float4 pa = f4z, pb = f4z, pt = make_float4(1,1,1,1), pf = f4z;
    if (valid) {
        pa = *(const float4*)&alpha1[hbase];
        pb = *(const float4*)&beta1[hbase];
        pt = *(const float4*)&thr1[hbase];
        pf = *(const float4*)&bfb[hbase];
    }
    // rowsum over j=0..199 for this lane's 4 h (junk for invalid lanes, unused)
    float4 rs = f4z;
    for (int j = 0; j < NH; j++) {
        float4 v = *((const float4*)(sWfb + j * NH) + rowoff);
        rs.x += v.x; rs.y += v.y; rs.z += v.z; rs.w += v.w;
    }
    float rs2 = 0.f, a2p = 0.f, b2p = 0.f, t2p = 1.f, bb2 = 0.f;
    if (w == 1) {
        for (int j = 0; j < NH; j++) rs2 += sW2[j * NOUT + lane];
        if (isO) { a2p = alpha2[lane]; b2p = beta2[lane]; t2p = thr2[lane]; bb2 = b2[lane]; }
    }

    float4 syn = f4z, mem = f4z;
    float syn2 = 0.f, mem2 = 0.f, rmax = __int_as_float(0xff800000u);

    const float* ffbase = g_ff + (size_t)b * TT * NH;
    float4 ff = valid ? *(const float4*)&ffbase[hbase] : f4z;

    const uint2* seg0q = (const uint2*)slist;
    const uint2* seg1q = (const uint2*)(slist + SEG1_OFF);
    int pit0 = 0, pit1 = 0, mode_p = 0;

    union { unsigned long long u; float2 f; } cv;

    for (int t = 0; t < TT; t++) {
        // prefetch next ff
        float4 nf = f4z;
        if (valid && t + 1 < TT) nf = *(const float4*)&ffbase[(t + 1) * NH + hbase];

        // ---- gather over both segments (software-pipelined) ----
        unsigned long long g0 = 0, g1 = 0, g2 = 0, g3 = 0;   // pos{0,1}->g0,g1 ; pos{2,3}->g2,g3
        float ac2a = 0.f, ac2b = 0.f;

        if (w == 0) {
            uint2 uc = seg0q[0];
            for (int k = 0; k < pit0; k++) {
                uint2 un = seg0q[k + 1];
                int j0 = uc.x & 0xffff, j1 = uc.x >> 16, j2 = uc.y & 0xffff, j3 = uc.y >> 16;
                ulonglong2 v0 = *((const ulonglong2*)(sWfb + j0 * NH) + lane);
                ulonglong2 v1 = *((const ulonglong2*)(sWfb + j1 * NH) + lane);
                ulonglong2 v2 = *((const ulonglong2*)(sWfb + j2 * NH) + lane);
                ulonglong2 v3 = *((const ulonglong2*)(sWfb + j3 * NH) + lane);
                ADD2(g0, v0.x); ADD2(g1, v0.y);
                ADD2(g0, v1.x); ADD2(g1, v1.y);
                ADD2(g2, v2.x); ADD2(g3, v2.y);
                ADD2(g2, v3.x); ADD2(g3, v3.y);
                uc = un;
            }
            uc = seg1q[0];
            for (int k = 0; k < pit1; k++) {
                uint2 un = seg1q[k + 1];
                int j0 = uc.x & 0xffff, j1 = uc.x >> 16, j2 = uc.y & 0xffff, j3 = uc.y >> 16;
                ulonglong2 v0 = *((const ulonglong2*)(sWfb + j0 * NH) + lane);
                ulonglong2 v1 = *((const ulonglong2*)(sWfb + j1 * NH) + lane);
                ulonglong2 v2 = *((const ulonglong2*)(sWfb + j2 * NH) + lane);
                ulonglong2 v3 = *((const ulonglong2*)(sWfb + j3 * NH) + lane);
                ADD2(g0, v0.x); ADD2(g1, v0.y);
                ADD2(g0, v1.x); ADD2(g1, v1.y);
                ADD2(g2, v2.x); ADD2(g3, v2.y);
                ADD2(g2, v3.x); ADD2(g3, v3.y);
                uc = un;
            }
        } else {
            uint2 uc = seg0q[0];
            for (int k = 0; k < pit0; k++) {
                uint2 un = seg0q[k + 1];
                int j0 = uc.x & 0xffff, j1 = uc.x >> 16, j2 = uc.y & 0xffff, j3 = uc.y >> 16;
                ulonglong2 v0 = *((const ulonglong2*)(sWfb + j0 * NH) + 32 + lane);
                ulonglong2 v1 = *((const ulonglong2*)(sWfb + j1 * NH) + 32 + lane);
                ulonglong2 v2 = *((const ulonglong2*)(sWfb + j2 * NH) + 32 + lane);
                ulonglong2 v3 = *((const ulonglong2*)(sWfb + j3 * NH) + 32 + lane);
                float w0 = sW2[j0 * NOUT + lane], w1 = sW2[j1 * NOUT + lane];
                float w2v = sW2[j2 * NOUT + lane], w3 = sW2[j3 * NOUT + lane];
                ADD2(g0, v0.x); ADD2(g1, v0.y);
                ADD2(g0, v1.x); ADD2(g1, v1.y);
                ADD2(g2, v2.x); ADD2(g3, v2.y);
                ADD2(g2, v3.x); ADD2(g3, v3.y);
                ac2a += w0 + w1; ac2b += w2v + w3;
                uc = un;
            }
            uc = seg1q[0];
            for (int k = 0; k < pit1; k++) {
                uint2 un = seg1q[k + 1];
                int j0 = uc.x & 0xffff, j1 = uc.x >> 16, j2 = uc.y & 0xffff, j3 = uc.y >> 16;
                ulonglong2 v0 = *((const ulonglong2*)(sWfb + j0 * NH) + 32 + lane);
                ulonglong2 v1 = *((const ulonglong2*)(sWfb + j1 * NH) + 32 + lane);
                ulonglong2 v2 = *((const ulonglong2*)(sWfb + j2 * NH) + 32 + lane);
                ulonglong2 v3 = *((const ulonglong2*)(sWfb + j3 * NH) + 32 + lane);
                float w0 = sW2[j0 * NOUT + lane], w1 = sW2[j1 * NOUT + lane];
                float w2v = sW2[j2 * NOUT + lane], w3 = sW2[j3 * NOUT + lane];
                ADD2(g0, v0.x); ADD2(g1, v0.y);
                ADD2(g0, v1.x); ADD2(g1, v1.y);
                ADD2(g2, v2.x); ADD2(g3, v2.y);
                ADD2(g2, v3.x); ADD2(g3, v3.y);
                ac2a += w0 + w1; ac2b += w2v + w3;
                uc = un;
            }
        }

        // unpack: h0 = g0.lo+g2.lo, h1 = g0.hi+g2.hi, h2 = g1.lo+g3.lo, h3 = g1.hi+g3.hi
        float4 g;
        cv.u = g0; g.x = cv.f.x;  g.y = cv.f.y;
        cv.u = g2; g.x += cv.f.x; g.y += cv.f.y;
        cv.u = g1; g.z = cv.f.x;  g.w = cv.f.y;
        cv.u = g3; g.z += cv.f.x; g.w += cv.f.y;

        // ---- layer-1 state update ----
        float4 cur;
        if (mode_p) { cur.x = rs.x - g.x; cur.y = rs.y - g.y; cur.z = rs.z - g.z; cur.w = rs.w - g.w; }
        else        { cur = g; }
        cur.x += ff.x + pf.x; cur.y += ff.y + pf.y; cur.z += ff.z + pf.z; cur.w += ff.w + pf.w;
        float r;
        syn.x = pa.x * syn.x + cur.x; r = (mem.x > pt.x) ? pt.x : 0.f; mem.x = pb.x * mem.x + syn.x - r;
        syn.y = pa.y * syn.y + cur.y; r = (mem.y > pt.y) ? pt.y : 0.f; mem.y = pb.y * mem.y + syn.y - r;
        syn.z = pa.z * syn.z + cur.z; r = (mem.z > pt.z) ? pt.z : 0.f; mem.z = pb.z * mem.z + syn.z - r;
        syn.w = pa.w * syn.w + cur.w; r = (mem.w > pt.w) ? pt.w : 0.f; mem.w = pb.w * mem.w + syn.w - r;
        bool s0 = valid && (mem.x > pt.x);
        bool s1 = valid && (mem.y > pt.y);
        bool s2 = valid && (mem.z > pt.z);
        bool s3 = valid && (mem.w > pt.w);

        // ---- layer-2 update for step t-1 (deferred; list was (t-1)'s) ----
        if (t > 0 && isO) {
            float a2 = ac2a + ac2b;
            float cur2 = bb2 + (mode_p ? (rs2 - a2) : a2);
            syn2 = a2p * syn2 + cur2;
            float r2 = (mem2 > t2p) ? t2p : 0.f;
            mem2 = b2p * mem2 + syn2 - r2;
            rmax = fmaxf(rmax, mem2);
        }

        // ---- count spikes, decide mode ----
        int myc = (int)s0 + (int)s1 + (int)s2 + (int)s3;
        int totw = __reduce_add_sync(0xffffffffu, myc);
        if (lane == 0) scnt[w] = totw;
        __syncthreads();                     // #1: gathers done, counts visible
        int c0 = scnt[0], c1 = scnt[1];
        int mode = (c0 + c1) > 100;

        // ---- build own segment (spikers or non-spikers) ----
        unsigned short* seg = (w == 0) ? slist : (slist + SEG1_OFF);
        int nc = 0; unsigned m; bool mine;
        mine = mode ? (valid && !s0) : s0;
        m = __ballot_sync(0xffffffffu, mine);
        if (mine) seg[__popc(m & lt)] = (unsigned short)hbase;
        nc = __popc(m);
        mine = mode ? (valid && !s1) : s1;
        m = __ballot_sync(0xffffffffu, mine);
        if (mine) seg[nc + __popc(m & lt)] = (unsigned short)(hbase + 1);
        nc += __popc(m);
        mine = mode ? (valid && !s2) : s2;
        m = __ballot_sync(0xffffffffu, mine);
        if (mine) seg[nc + __popc(m & lt)] = (unsigned short)(hbase + 2);
        nc += __popc(m);
        mine = mode ? (valid && !s3) : s3;
        m = __ballot_sync(0xffffffffu, mine);
        if (mine) seg[nc + __popc(m & lt)] = (unsigned short)(hbase + 3);
        nc += __popc(m);
        if (lane == 0) { int cp = nc; while (cp & 3) seg[cp++] = 200; }   // pad -> zero row

        // next-step uniform list info (derived, no extra smem pass)
        int n0 = mode ? (128 - c0) : c0;
        int n1 = mode ? (72 - c1) : c1;
        pit0 = (n0 + 3) >> 2; pit1 = (n1 + 3) >> 2; mode_p = mode;
        __syncthreads();                     // #2: list ready
        ff = nf;
    }

    // ---- epilogue: layer-2 for step TT-1 + softmax (warp1) ----
    if (w == 1) {
        float ac2a = 0.f, ac2b = 0.f;
        for (int k = 0; k < pit0; k++) {
            uint2 u = seg0q[k];
            int j0 = u.x & 0xffff, j1 = u.x >> 16, j2 = u.y & 0xffff, j3 = u.y >> 16;
            ac2a += sW2[j0 * NOUT + lane] + sW2[j1 * NOUT + lane];
            ac2b += sW2[j2 * NOUT + lane] + sW2[j3 * NOUT + lane];
        }
        for (int k = 0; k < pit1; k++) {
            uint2 u = seg1q[k];
            int j0 = u.x & 0xffff, j1 = u.x >> 16, j2 = u.y & 0xffff, j3 = u.y >> 16;
            ac2a += sW2[j0 * NOUT + lane] + sW2[j1 * NOUT + lane];
            ac2b += sW2[j2 * NOUT + lane] + sW2[j3 * NOUT + lane];
        }
        if (isO) {
            float a2 = ac2a + ac2b;
            float cur2 = bb2 + (mode_p ? (rs2 - a2) : a2);
            syn2 = a2p * syn2 + cur2;
            float r2 = (mem2 > t2p) ? t2p : 0.f;
            mem2 = b2p * mem2 + syn2 - r2;
            rmax = fmaxf(rmax, mem2);
        }
        float v = isO ? rmax : __int_as_float(0xff800000u);
#pragma unroll
        for (int d = 16; d; d >>= 1) v = fmaxf(v, __shfl_xor_sync(0xffffffffu, v, d));
        float e = isO ? expf(rmax - v) : 0.f;
        float ssum = e;
#pragma unroll
        for (int d = 16; d; d >>= 1) ssum += __shfl_xor_sync(0xffffffffu, ssum, d);
        if (isO) out[b * NOUT + lane] = e / ssum;
    }
}

// ===========================================================================
extern "C" void kernel_launch(void* const* d_in, const int* in_sizes, int n_in,
                              void* d_out, int out_size)
{
    const float* x      = (const float*)d_in[0];
    const float* W1     = (const float*)d_in[1];
    const float* b1     = (const float*)d_in[2];
    const float* Wfb    = (const float*)d_in[3];
    const float* bfb    = (const float*)d_in[4];
    const float* W2     = (const float*)d_in[5];
    const float* b2     = (const float*)d_in[6];
    const float* alpha1 = (const float*)d_in[7];
    const float* beta1  = (const float*)d_in[8];
    const float* thr1   = (const float*)d_in[9];
    const float* alpha2 = (const float*)d_in[10];
    const float* beta2  = (const float*)d_in[11];
    const float* thr2   = (const float*)d_in[12];
    float* out = (float*)d_out;

    cudaFuncSetAttribute(k_ff,  cudaFuncAttributeMaxDynamicSharedMemorySize, P1_SMEM);
    cudaFuncSetAttribute(k_snn, cudaFuncAttributeMaxDynamicSharedMemorySize, P2_SMEM);

    k_compact<<<NROWS / 8, 256>>>(x);
    k_ff<<<dim3(4, P1_GROUPS), 512, P1_SMEM>>>(W1, b1);
    k_snn<<<BB, 64, P2_SMEM>>>(Wfb, bfb, W2, b2,
                               alpha1, beta1, thr1,
                               alpha2, beta2, thr2, out);
}

// round 12
// speedup vs baseline: 1.7911x; 1.3940x over previous
#include <cuda_runtime.h>
#include <cstdint>

#define BB   128
#define TT   500
#define NIN  700
#define NH   200
#define NOUT 20
#define NROWS (BB*TT)          // 64000
#define CAP  256               // max active inputs per row (x4-padded with 700)

// -------- scratch (static __device__ allocations: allowed) -----------------
__device__ unsigned short g_idx[(size_t)NROWS * CAP];
__device__ int            g_cnt[NROWS];
__device__ float          g_ff[(size_t)NROWS * NH];     // cur1_ff = x@W1^T + b1

// ===========================================================================
// P0: compact active input indices per (b,t) row; pad list to x4 with 700.
// DRAM-bound (~35us floor).
// ===========================================================================
__global__ __launch_bounds__(256) void k_compact(const float* __restrict__ x)
{
    int wid  = threadIdx.x >> 5, lane = threadIdx.x & 31;
    int row  = blockIdx.x * 8 + wid;
    if (row >= NROWS) return;
    const float* xr = x + (size_t)row * NIN;
    unsigned short* out = g_idx + (size_t)row * CAP;
    unsigned lt = (1u << lane) - 1u;
    int cnt = 0;
#pragma unroll
    for (int c = 0; c < (NIN + 31) / 32; c++) {
        int i = c * 32 + lane;
        float v = (i < NIN) ? xr[i] : 0.f;
        bool a = v > 0.5f;
        unsigned m = __ballot_sync(0xffffffffu, a);
        if (a) {
            int pos = cnt + __popc(m & lt);
            if (pos < CAP) out[pos] = (unsigned short)i;
        }
        cnt += __popc(m);
    }
    if (lane == 0) {
        int c = (cnt < CAP) ? cnt : CAP;
        g_cnt[row] = c;
        int cp = c;
        while ((cp & 3) && cp < CAP) out[cp++] = 700;   // pad -> zero row
    }
}

// ===========================================================================
// P1: cur1_ff (unchanged from R7: ~293us measured).
// ===========================================================================
#define P1_HC     50
#define P1_STRIDE 52
#define P1_WSLOT  64
#define OFF_BUF   (701 * P1_STRIDE)
#define P1_SMEM   ((OFF_BUF + 16 * P1_WSLOT * 2) * 4)
#define P1_GROUPS 128
#define P1_RPC    (NROWS / P1_GROUPS)

__global__ __launch_bounds__(512) void k_ff(const float* __restrict__ W1,
                                            const float* __restrict__ b1)
{
    extern __shared__ float s[];
    int tid = threadIdx.x, wid = tid >> 5, lane = tid & 31;
    int h0 = blockIdx.x * P1_HC;

    for (int i = tid; i < P1_HC * NIN; i += 512) {
        int hh = i / NIN, n = i - hh * NIN;
        s[n * P1_STRIDE + hh] = W1[(h0 + hh) * NIN + n];
    }
    for (int i = tid; i < P1_STRIDE; i += 512) s[700 * P1_STRIDE + i] = 0.f;
    __syncthreads();

    uint2* swbuf = (uint2*)(s + OFF_BUF) + wid * P1_WSLOT;
    const uint2* sbuf2 = (const uint2*)swbuf;

    int hh2 = 2 * lane;
    bool act = (lane < 25);
    float bb0 = 0.f, bb1 = 0.f;
    if (act) { bb0 = b1[h0 + hh2]; bb1 = b1[h0 + hh2 + 1]; }

    int base = blockIdx.y * P1_RPC;
    int lim  = base + P1_RPC; if (lim > NROWS) lim = NROWS;

    int row = base + wid;
    if (row >= lim) return;

    int  cnt_c = g_cnt[row];
    uint2 rA   = ((const uint2*)(g_idx + (size_t)row * CAP))[lane];

    while (row < lim) {
        int rn = row + 16;
        int  cnt_n = 0;
        uint2 nA = make_uint2(0u, 0u);
        if (rn < lim) {
            cnt_n = g_cnt[rn];
            nA = ((const uint2*)(g_idx + (size_t)rn * CAP))[lane];
        }

        swbuf[lane] = rA;
        if (cnt_c > 128)
            swbuf[32 + lane] = ((const uint2*)(g_idx + (size_t)row * CAP))[32 + lane];
        __syncwarp();

        float c0a = 0.f, c1a = 0.f, c0b = 0.f, c1b = 0.f;
        int it = (cnt_c + 3) >> 2;
#pragma unroll 2
        for (int k = 0; k < it; k++) {
            uint2 u = sbuf2[k];
            int j0 = u.x & 0xffff, j1 = u.x >> 16;
            int j2 = u.y & 0xffff, j3 = u.y >> 16;
            if (act) {
                float2 v0 = *(const float2*)&s[j0 * P1_STRIDE + hh2];
                float2 v1 = *(const float2*)&s[j1 * P1_STRIDE + hh2];
                float2 v2 = *(const float2*)&s[j2 * P1_STRIDE + hh2];
                float2 v3 = *(const float2*)&s[j3 * P1_STRIDE + hh2];
                c0a += v0.x + v1.x;  c0b += v2.x + v3.x;
                c1a += v0.y + v1.y;  c1b += v2.y + v3.y;
            }
        }
        if (act) {
            float2 o; o.x = (c0a + c0b) + bb0; o.y = (c1a + c1b) + bb1;
            *(float2*)&g_ff[(size_t)row * NH + h0 + hh2] = o;
        }
        __syncwarp();

        row = rn; cnt_c = cnt_n; rA = nA;
    }
}

// ===========================================================================
// P2: R5 structure (best measured: 774us) + PER-SEGMENT COMPLEMENT.
// 512 threads, 4 groups; group g gathers list segment g. Segment wg covers
// h in [64*wg, 64*wg+64) (wg<3) or [192,200) (wg=3). Each segment stores
// spikers OR non-spikers (whichever is shorter; mode bit in count word),
// capping every segment at <=32 entries and balancing groups.
// Consumers: partial = mode ? rowsum_seg - sum : sum.
// ===========================================================================
#define SEG 72
#define OFF_W2    (201*NH)
#define OFF_LIST  (OFF_W2 + 201*NOUT)
#define OFF_CNT   (OFF_LIST + 2*4*SEG)
#define OFF_P2    (OFF_CNT + 8)
#define OFF_RS2   (OFF_P2 + 4*NOUT)              // [4][20] W2 segment rowsums
#define OFF_P1    (OFF_RS2 + 4*NOUT)
#define P2_SMEM   ((OFF_P1 + 3*NH) * 4)

__global__ __launch_bounds__(512) void k_snn(
    const float* __restrict__ Wfb,  const float* __restrict__ bfb,
    const float* __restrict__ W2,   const float* __restrict__ b2,
    const float* __restrict__ alpha1, const float* __restrict__ beta1,
    const float* __restrict__ thr1,
    const float* __restrict__ alpha2, const float* __restrict__ beta2,
    const float* __restrict__ thr2,
    float* __restrict__ out)
{
    extern __shared__ float sm[];
    float* sWfb  = sm;
    float* sW2   = sm + OFF_W2;
    int*   slist = (int*)(sm + OFF_LIST);
    int*   scnt  = (int*)(sm + OFF_CNT);
    float* spart2= sm + OFF_P2;
    float* srs2  = sm + OFF_RS2;
    float* spart1= sm + OFF_P1;

    int tid = threadIdx.x, lane = tid & 31;
    int g = tid >> 7, tid_l = tid & 127;
    int wg = (tid_l) >> 5;
    int b = blockIdx.x;

    for (int i = tid; i < NH * NH; i += 512) {
        int h = i / NH, j = i - h * NH;
        sWfb[j * NH + h] = Wfb[i];
    }
    for (int i = tid; i < NH; i += 512) sWfb[200 * NH + i] = 0.f;
    for (int i = tid; i < NOUT * NH; i += 512) {
        int o = i / NH, j = i - o * NH;
        sW2[j * NOUT + o] = W2[i];
    }
    for (int i = tid; i < NOUT; i += 512) sW2[200 * NOUT + i] = 0.f;
    if (tid < 8) scnt[tid] = 0;

    float syn0 = 0.f, syn1v = 0.f, mem0 = 0.f, mem1v = 0.f;
    float a0 = 0.f, a1 = 0.f, be0 = 0.f, be1 = 0.f;
    float th0 = 1.f, th1 = 1.f, bf0 = 0.f, bf1 = 0.f;
    const float* ffp = g_ff;
    if (g == 0 && tid_l < 100) {
        int h = 2 * tid_l;
        a0 = alpha1[h]; a1 = alpha1[h + 1];
        be0 = beta1[h]; be1 = beta1[h + 1];
        th0 = thr1[h];  th1 = thr1[h + 1];
        bf0 = bfb[h];   bf1 = bfb[h + 1];
        ffp = g_ff + (size_t)b * TT * NH + h;
    }
    float s2 = 0.f, m2 = 0.f;
    float a2l = 0.f, be2l = 0.f, th2l = 1.f, b2l = 0.f;
    float rmax = __int_as_float(0xff800000u);
    if (g == 1 && tid_l < 20) {
        a2l = alpha2[tid_l]; be2l = beta2[tid_l]; th2l = thr2[tid_l]; b2l = b2[tid_l];
    }
    __syncthreads();                              // weights in smem

    const float2* wf2 = (const float2*)sWfb;      // [j*100 + tid_l]

    // ---- one-time segment rowsums ----
    // layer-1: per-thread rowsum of own group's segment for its 2 h
    float rs0 = 0.f, rs1 = 0.f;
    if (tid_l < 100) {
        int j0 = 64 * g, j1 = (g == 3) ? 200 : (64 * g + 64);
        float e0 = 0.f, e1 = 0.f, o0 = 0.f, o1 = 0.f;
        for (int j = j0; j < j1; j += 2) {
            float2 va = wf2[j * 100 + tid_l];
            float2 vb = wf2[(j + 1) * 100 + tid_l];
            e0 += va.x; e1 += va.y; o0 += vb.x; o1 += vb.y;
        }
        rs0 = e0 + o0; rs1 = e1 + o1;
    }
    // layer-2: srs2[gg][oo] = sum over seg gg of W2^T[j][oo]
    if (tid < 80) {
        int gg = tid / 20, oo = tid - gg * 20;
        int j0 = 64 * gg, j1 = (gg == 3) ? 200 : (64 * gg + 64);
        float acca = 0.f, accb = 0.f;
        for (int j = j0; j + 1 < j1; j += 2) {
            acca += sW2[j * NOUT + oo];
            accb += sW2[(j + 1) * NOUT + oo];
        }
        srs2[tid] = acca + accb;
    }
    __syncthreads();                              // srs2 ready

    float ff0 = 0.f, ff1 = 0.f, nf0 = 0.f, nf1 = 0.f;
    if (g == 0 && tid_l < 100) { float2 v = *(const float2*)ffp; ff0 = v.x; ff1 = v.y; }

    for (int t = 0; t < TT; t++) {
        int p = t & 1, q = p ^ 1;

        if (g == 0 && tid_l < 100 && t + 1 < TT) {
            float2 v = *(const float2*)(ffp + (size_t)(t + 1) * NH);
            nf0 = v.x; nf1 = v.y;
        }

        // ---- gather phase: group g sums its segment of list[p] ----
        float c0 = 0.f, c1 = 0.f;
        int sv = scnt[p * 4 + g];
        int cseg = sv & 0xffff, md = sv >> 16;
        if (tid_l < 100) {
            const int4* p4 = (const int4*)&slist[(p * 4 + g) * SEG];
            int it = (cseg + 3) >> 2;
            float d0 = 0.f, d1 = 0.f;
#pragma unroll 2
            for (int k = 0; k < it; k++) {
                int4 jj = p4[k];
                float2 v0 = wf2[jj.x * 100 + tid_l];
                float2 v1 = wf2[jj.y * 100 + tid_l];
                float2 v2 = wf2[jj.z * 100 + tid_l];
                float2 v3 = wf2[jj.w * 100 + tid_l];
                c0 += v0.x + v1.x;  d0 += v2.x + v3.x;
                c1 += v0.y + v1.y;  d1 += v2.y + v3.y;
            }
            c0 += d0; c1 += d1;
            if (md) { c0 = rs0 - c0; c1 = rs1 - c1; }
            if (g > 0) {
                float2 o; o.x = c0; o.y = c1;
                ((float2*)spart1)[(g - 1) * 100 + tid_l] = o;
            }
        } else if (wg == 3 && lane >= 4 && lane < 24) {
            int o = lane - 4;
            float pp = 0.f, qq = 0.f;
            const int4* p4 = (const int4*)&slist[(p * 4 + g) * SEG];
            int it = (cseg + 3) >> 2;
            for (int k = 0; k < it; k++) {
                int4 jj = p4[k];
                pp += sW2[jj.x * NOUT + o] + sW2[jj.y * NOUT + o];
                qq += sW2[jj.z * NOUT + o] + sW2[jj.w * NOUT + o];
            }
            float tot = pp + qq;
            spart2[g * NOUT + o] = md ? (srs2[g * NOUT + o] - tot) : tot;
        }
        __syncthreads();                          // #1: partials ready

        // ---- group 0: combine + state update + build list[q] ----
        bool sp0 = false, sp1 = false;
        if (g == 0) {
            if (tid_l < 100) {
                float2 pa = ((const float2*)spart1)[tid_l];
                float2 pb = ((const float2*)spart1)[100 + tid_l];
                float2 pc = ((const float2*)spart1)[200 + tid_l];
                c0 += (pa.x + pb.x) + pc.x + ff0 + bf0;
                c1 += (pa.y + pb.y) + pc.y + ff1 + bf1;
                syn0  = a0 * syn0  + c0;
                syn1v = a1 * syn1v + c1;
                float r0 = (mem0  > th0) ? th0 : 0.f;
                float r1 = (mem1v > th1) ? th1 : 0.f;
                mem0  = be0 * mem0  + syn0  - r0;
                mem1v = be1 * mem1v + syn1v - r1;
                sp0 = mem0  > th0;
                sp1 = mem1v > th1;
            }
            // per-segment complement decision + list build
            unsigned m0 = __ballot_sync(0xffffffffu, sp0);
            unsigned m1 = __ballot_sync(0xffffffffu, sp1);
            int cnt_sp = __popc(m0) + __popc(m1);
            int seg_h  = (wg < 3) ? 64 : 8;
            int mdq    = (2 * cnt_sp > seg_h) ? 1 : 0;
            bool valid = (wg < 3) || (lane < 4);
            bool w0s = mdq ? (valid && !sp0) : sp0;
            bool w1s = mdq ? (valid && !sp1) : sp1;
            unsigned M0 = __ballot_sync(0xffffffffu, w0s);
            unsigned M1 = __ballot_sync(0xffffffffu, w1s);
            int* seg = &slist[(q * 4 + wg) * SEG];
            unsigned lt = (1u << lane) - 1u;
            int c0n = __popc(M0);
            int cl  = c0n + __popc(M1);
            if (w0s) seg[__popc(M0 & lt)]       = 2 * tid_l;
            if (w1s) seg[c0n + __popc(M1 & lt)] = 2 * tid_l + 1;
            if (lane == 0) {
                scnt[q * 4 + wg] = cl | (mdq << 16);
                int cp = cl;
                while (cp & 3) seg[cp++] = 200;   // pad -> zero row
            }
        }
        // ---- group 1: layer-2 finalize for step t-1 ----
        if (g == 1 && tid_l < 20 && t > 0) {
            float c2 = b2l + (spart2[tid_l] + spart2[NOUT + tid_l]) +
                             (spart2[2 * NOUT + tid_l] + spart2[3 * NOUT + tid_l]);
            s2 = a2l * s2 + c2;
            float r2 = (m2 > th2l) ? th2l : 0.f;
            m2 = be2l * m2 + s2 - r2;
            rmax = fmaxf(rmax, m2);
        }
        __syncthreads();                          // #2: list[q] ready
        ff0 = nf0; ff1 = nf1;
    }

    // epilogue: layer-2 for step TT-1 (all 4 segments, mode-aware)
    if (g == 1 && tid_l < 20) {
        int pbuf = TT & 1;
        float pp = 0.f;
        for (int w = 0; w < 4; w++) {
            int sv = scnt[pbuf * 4 + w];
            int c = sv & 0xffff, md = sv >> 16;
            const int4* p4 = (const int4*)&slist[(pbuf * 4 + w) * SEG];
            int it = (c + 3) >> 2;
            float sseg = 0.f;
            for (int k = 0; k < it; k++) {
                int4 jj = p4[k];
                sseg += (sW2[jj.x * NOUT + tid_l] + sW2[jj.y * NOUT + tid_l]) +
                        (sW2[jj.z * NOUT + tid_l] + sW2[jj.w * NOUT + tid_l]);
            }
            pp += md ? (srs2[w * NOUT + tid_l] - sseg) : sseg;
        }
        float c2 = b2l + pp;
        s2 = a2l * s2 + c2;
        float r2 = (m2 > th2l) ? th2l : 0.f;
        m2 = be2l * m2 + s2 - r2;
        rmax = fmaxf(rmax, m2);
    }
    __syncthreads();

    if ((tid >> 5) == 4) {
        float v = (lane < 20) ? rmax : __int_as_float(0xff800000u);
#pragma unroll
        for (int d = 16; d; d >>= 1) v = fmaxf(v, __shfl_xor_sync(0xffffffffu, v, d));
        float e = (lane < 20) ? expf(rmax - v) : 0.f;
        float ssum = e;
#pragma unroll
        for (int d = 16; d; d >>= 1) ssum += __shfl_xor_sync(0xffffffffu, ssum, d);
        if (lane < 20) out[b * NOUT + lane] = e / ssum;
    }
}

// ===========================================================================
extern "C" void kernel_launch(void* const* d_in, const int* in_sizes, int n_in,
                              void* d_out, int out_size)
{
    const float* x      = (const float*)d_in[0];
    const float* W1     = (const float*)d_in[1];
    const float* b1     = (const float*)d_in[2];
    const float* Wfb    = (const float*)d_in[3];
    const float* bfb    = (const float*)d_in[4];
    const float* W2     = (const float*)d_in[5];
    const float* b2     = (const float*)d_in[6];
    const float* alpha1 = (const float*)d_in[7];
    const float* beta1  = (const float*)d_in[8];
    const float* thr1   = (const float*)d_in[9];
    const float* alpha2 = (const float*)d_in[10];
    const float* beta2  = (const float*)d_in[11];
    const float* thr2   = (const float*)d_in[12];
    float* out = (float*)d_out;

    cudaFuncSetAttribute(k_ff,  cudaFuncAttributeMaxDynamicSharedMemorySize, P1_SMEM);
    cudaFuncSetAttribute(k_snn, cudaFuncAttributeMaxDynamicSharedMemorySize, P2_SMEM);

    k_compact<<<NROWS / 8, 256>>>(x);
    k_ff<<<dim3(4, P1_GROUPS), 512, P1_SMEM>>>(W1, b1);
    k_snn<<<BB, 512, P2_SMEM>>>(Wfb, bfb, W2, b2,
                                alpha1, beta1, thr1,
                                alpha2, beta2, thr2, out);
}